// round 1
// baseline (speedup 1.0000x reference)
#include <cuda_runtime.h>
#include <math.h>

// Problem constants
#define NN 64
#define TT 128
#define DD 512
#define HH 1024
#define G4 4096   // 4*H

// ---------------- scratch (device globals; no allocations) ----------------
__device__ float g_Xa[(NN * TT) * G4];     // 128 MB: x@Wx + b, rows (n*T + t)
__device__ float g_P[(NN * 16) * G4];      // 16 MB: packed [n][l][c][gate]
__device__ float g_WhT[HH * G4];           // 16 MB: packed [k][c][gate]
__device__ float g_A2[(NN * 16) * HH];     // 4 MB:  A2[(n*16+l)][k] = A[n][k][l]
__device__ float g_hbuf[2][NN * HH];
__device__ float g_cbuf[2][NN * HH];
__device__ float g_scores[3][NN * 16];     // raw (unscaled) h·Af accumulators

// ---------------- weight packing ----------------
__global__ void __launch_bounds__(256) pack_wh_kernel(const float* __restrict__ Wh) {
    int idx = blockIdx.x * 256 + threadIdx.x;   // 0 .. 1M-1 over (k, c)
    int k = idx >> 10;
    int c = idx & 1023;
    const float* row = Wh + k * G4;
    float4 v;
    v.x = row[c];
    v.y = row[1024 + c];
    v.z = row[2048 + c];
    v.w = row[3072 + c];
    *(float4*)&g_WhT[idx * 4] = v;
}

// A2[(n*16+l)][k] = A[(n*1024+k)*16 + l]
__global__ void __launch_bounds__(256) transposeA_kernel(const float* __restrict__ A) {
    int idx = blockIdx.x * 256 + threadIdx.x;   // output index, 0 .. 1M-1
    int r = idx >> 10;           // n*16 + l
    int k = idx & 1023;
    int n = r >> 4;
    int l = r & 15;
    g_A2[idx] = A[((n << 10) + k) * 16 + l];
}

// ---------------- generic tiled SGEMM: BM=128, BN=64, BK=16, 256 thr, 8x4 ----
// MODE 0: C = g_Xa, C[row*N+col] = acc + bias[col]
// MODE 1: A = g_A2, C = g_P packed: out[((row*1024)+(col&1023))*4 + (col>>10)]
template <int MODE>
__global__ void __launch_bounds__(256) sgemm_kernel(const float* __restrict__ Ain,
                                                    const float* __restrict__ B,
                                                    const float* __restrict__ bias,
                                                    int M, int N, int K) {
    __shared__ float As[16][128];
    __shared__ float Bs[16][64];

    const float* Amat = (MODE == 1) ? (const float*)g_A2 : Ain;
    float* C = (MODE == 1) ? (float*)g_P : (float*)g_Xa;

    const int tid = threadIdx.x;
    const int trow = tid >> 4;       // 0..15
    const int tcol = tid & 15;       // 0..15
    const int m0 = blockIdx.y * 128;
    const int n0 = blockIdx.x * 64;

    float acc[8][4];
#pragma unroll
    for (int i = 0; i < 8; i++)
#pragma unroll
        for (int j = 0; j < 4; j++) acc[i][j] = 0.0f;

    for (int k0 = 0; k0 < K; k0 += 16) {
        // A tile: 128x16 -> transposed As[k][m]
#pragma unroll
        for (int p = 0; p < 2; p++) {
            int i = tid + p * 256;            // 0..511 float4 slots
            int m = i >> 2;
            int kq = (i & 3) * 4;
            float4 v = *(const float4*)&Amat[(long)(m0 + m) * K + k0 + kq];
            As[kq + 0][m] = v.x;
            As[kq + 1][m] = v.y;
            As[kq + 2][m] = v.z;
            As[kq + 3][m] = v.w;
        }
        // B tile: 16x64
        {
            int k = tid >> 4;
            int nq = (tid & 15) * 4;
            *(float4*)&Bs[k][nq] = *(const float4*)&B[(long)(k0 + k) * N + n0 + nq];
        }
        __syncthreads();

#pragma unroll
        for (int kk = 0; kk < 16; kk++) {
            float a0[8];
            float4 av0 = *(float4*)&As[kk][trow * 8];
            float4 av1 = *(float4*)&As[kk][trow * 8 + 4];
            a0[0] = av0.x; a0[1] = av0.y; a0[2] = av0.z; a0[3] = av0.w;
            a0[4] = av1.x; a0[5] = av1.y; a0[6] = av1.z; a0[7] = av1.w;
            float4 bv = *(float4*)&Bs[kk][tcol * 4];
            float b0[4] = {bv.x, bv.y, bv.z, bv.w};
#pragma unroll
            for (int i = 0; i < 8; i++)
#pragma unroll
                for (int j = 0; j < 4; j++) acc[i][j] += a0[i] * b0[j];
        }
        __syncthreads();
    }

#pragma unroll
    for (int i = 0; i < 8; i++) {
        int row = m0 + trow * 8 + i;
        int colb = n0 + tcol * 4;
        if (MODE == 0) {
            float4 bv = *(const float4*)&bias[colb];
            float4 o;
            o.x = acc[i][0] + bv.x;
            o.y = acc[i][1] + bv.y;
            o.z = acc[i][2] + bv.z;
            o.w = acc[i][3] + bv.w;
            *(float4*)&C[(long)row * N + colb] = o;
        } else {
#pragma unroll
            for (int j = 0; j < 4; j++) {
                int col = colb + j;
                int g = col >> 10;
                int cl = col & 1023;
                C[((long)row * 1024 + cl) * 4 + g] = acc[i][j];
            }
        }
    }
}

// ---------------- init: h0 = c0 = mean(Af), scores0 = h0·Af ----------------
__global__ void __launch_bounds__(256) init_kernel(const float* __restrict__ A) {
    const int n = blockIdx.x;
    const int tid = threadIdx.x;
    __shared__ float sc[256][16];

    float accl[16];
#pragma unroll
    for (int l = 0; l < 16; l++) accl[l] = 0.0f;

    for (int h = tid; h < HH; h += 256) {
        const float* ar = A + ((n << 10) + h) * 16;
        float a[16];
        float4 v0 = *(const float4*)&ar[0];
        float4 v1 = *(const float4*)&ar[4];
        float4 v2 = *(const float4*)&ar[8];
        float4 v3 = *(const float4*)&ar[12];
        a[0]=v0.x; a[1]=v0.y; a[2]=v0.z; a[3]=v0.w;
        a[4]=v1.x; a[5]=v1.y; a[6]=v1.z; a[7]=v1.w;
        a[8]=v2.x; a[9]=v2.y; a[10]=v2.z; a[11]=v2.w;
        a[12]=v3.x; a[13]=v3.y; a[14]=v3.z; a[15]=v3.w;
        float s = 0.0f;
#pragma unroll
        for (int l = 0; l < 16; l++) s += a[l];
        s *= (1.0f / 16.0f);
        g_hbuf[0][(n << 10) + h] = s;
        g_cbuf[0][(n << 10) + h] = s;
#pragma unroll
        for (int l = 0; l < 16; l++) accl[l] += s * a[l];
    }
#pragma unroll
    for (int l = 0; l < 16; l++) sc[tid][l] = accl[l];
    __syncthreads();
    if (tid < 16) {
        float s = 0.0f;
        for (int j = 0; j < 256; j++) s += sc[j][tid];
        g_scores[0][n * 16 + tid] = s;
        g_scores[1][n * 16 + tid] = 0.0f;
        g_scores[2][n * 16 + tid] = 0.0f;
    }
}

// ---------------- fused step: softmax + (h@Wh + w@P + Xa) + LSTM + next scores
__global__ void __launch_bounds__(256) step_kernel(int t, const float* __restrict__ A,
                                                   float* __restrict__ out) {
    const int tid = threadIdx.x;
    const int tx = tid & 15;         // c within block
    const int ty = tid >> 4;         // n-pair index
    const int cb = blockIdx.x;       // 0..63
    const int nb = blockIdx.y;       // 0..1
    const int c = cb * 16 + tx;
    const int nl0 = ty * 2;
    const int n0 = nb * 32 + nl0;
    const int n1 = n0 + 1;

    const int prev = t & 1;
    const int cur = prev ^ 1;
    const float* h_prev = g_hbuf[prev];
    const float* c_prev = g_cbuf[prev];
    const float* sc_in = g_scores[t % 3];
    float* sc_out = g_scores[(t + 1) % 3];
    float* sc_zero = g_scores[(t + 2) % 3];

    __shared__ float hs[32][128];
    __shared__ float ws[32][16];
    __shared__ float sred[512];

    // per-CTA redundant softmax over the 32 rows it owns
    if (tid < 32) {
        float s[16];
        float m = -1e30f;
#pragma unroll
        for (int l = 0; l < 16; l++) {
            s[l] = sc_in[(nb * 32 + tid) * 16 + l] * 0.03125f;  // 1/sqrt(1024)
            m = fmaxf(m, s[l]);
        }
        float sum = 0.0f;
#pragma unroll
        for (int l = 0; l < 16; l++) { s[l] = expf(s[l] - m); sum += s[l]; }
        float inv = 1.0f / sum;
#pragma unroll
        for (int l = 0; l < 16; l++) ws[tid][l] = s[l] * inv;
    }
    // zero the buffer that step t+1 will accumulate into
    if (cb == 0) {
        sc_zero[nb * 512 + tid] = 0.0f;
        sc_zero[nb * 512 + tid + 256] = 0.0f;
    }

    // init accumulators from precomputed Xa (+ bias already folded in)
    float acc[2][4];
    {
        const float* xa0 = g_Xa + ((long)(n0 * TT + t)) * G4 + c;
        const float* xa1 = g_Xa + ((long)(n1 * TT + t)) * G4 + c;
#pragma unroll
        for (int g = 0; g < 4; g++) {
            acc[0][g] = xa0[g << 10];
            acc[1][g] = xa1[g << 10];
        }
    }

    const float4* W4 = (const float4*)g_WhT;   // index: k*1024 + c

    // main recurrent GEMM: a += h_prev @ Wh
    for (int kc = 0; kc < HH; kc += 128) {
        __syncthreads();
#pragma unroll
        for (int i = 0; i < 4; i++) {
            int f = tid + i * 256;         // 0..1023 float4 slots (32n x 32kq)
            int nl = f >> 5;
            int kq = f & 31;
            *(float4*)&hs[nl][kq * 4] =
                *(const float4*)&h_prev[((nb * 32 + nl) << 10) + kc + kq * 4];
        }
        __syncthreads();

        for (int kk = 0; kk < 128; kk += 8) {
            float4 wv[8];
#pragma unroll
            for (int j = 0; j < 8; j++) wv[j] = W4[(kc + kk + j) * 1024 + c];
#pragma unroll
            for (int j = 0; j < 8; j++) {
                float h0v = hs[nl0][kk + j];
                float h1v = hs[nl0 + 1][kk + j];
                acc[0][0] += h0v * wv[j].x;
                acc[0][1] += h0v * wv[j].y;
                acc[0][2] += h0v * wv[j].z;
                acc[0][3] += h0v * wv[j].w;
                acc[1][0] += h1v * wv[j].x;
                acc[1][1] += h1v * wv[j].y;
                acc[1][2] += h1v * wv[j].z;
                acc[1][3] += h1v * wv[j].w;
            }
        }
    }

    // attention contribution: a += w @ P  (P packed [n][l][c][gate])
    const float4* P4 = (const float4*)g_P;
#pragma unroll
    for (int l = 0; l < 16; l++) {
        float w0 = ws[nl0][l];
        float w1 = ws[nl0 + 1][l];
        float4 p0 = P4[((n0 * 16 + l) << 10) + c];
        float4 p1 = P4[((n1 * 16 + l) << 10) + c];
        acc[0][0] += w0 * p0.x; acc[0][1] += w0 * p0.y;
        acc[0][2] += w0 * p0.z; acc[0][3] += w0 * p0.w;
        acc[1][0] += w1 * p1.x; acc[1][1] += w1 * p1.y;
        acc[1][2] += w1 * p1.z; acc[1][3] += w1 * p1.w;
    }

    // LSTM cell update + output write
    float hn[2];
#pragma unroll
    for (int r = 0; r < 2; r++) {
        int n = n0 + r;
        float ig = 1.0f / (1.0f + expf(-acc[r][0]));
        float fg = 1.0f / (1.0f + expf(-acc[r][1]));
        float og = 1.0f / (1.0f + expf(-acc[r][2]));
        float gg = tanhf(acc[r][3]);
        float cp = c_prev[(n << 10) + c];
        float cn = fg * cp + ig * gg;
        float h = og * tanhf(cn);
        g_cbuf[cur][(n << 10) + c] = cn;
        g_hbuf[cur][(n << 10) + c] = h;
        out[((long)(n * TT + t)) * HH + c] = h;
        hn[r] = h;
    }

    // next-step score partials: scores[n][l] += sum_c h_new[n][c] * A[n][c][l]
#pragma unroll
    for (int r = 0; r < 2; r++) {
        int n = n0 + r;
        const float* ar = A + (((long)(n << 10) + c)) * 16;
        float a[16];
        float4 v0 = *(const float4*)&ar[0];
        float4 v1 = *(const float4*)&ar[4];
        float4 v2 = *(const float4*)&ar[8];
        float4 v3 = *(const float4*)&ar[12];
        a[0]=v0.x; a[1]=v0.y; a[2]=v0.z; a[3]=v0.w;
        a[4]=v1.x; a[5]=v1.y; a[6]=v1.z; a[7]=v1.w;
        a[8]=v2.x; a[9]=v2.y; a[10]=v2.z; a[11]=v2.w;
        a[12]=v3.x; a[13]=v3.y; a[14]=v3.z; a[15]=v3.w;
#pragma unroll
        for (int l = 0; l < 16; l++) {
            float v = hn[r] * a[l];
            // reduce over the 16 tx lanes (halves of the warp stay separate)
            v += __shfl_xor_sync(0xffffffffu, v, 1);
            v += __shfl_xor_sync(0xffffffffu, v, 2);
            v += __shfl_xor_sync(0xffffffffu, v, 4);
            v += __shfl_xor_sync(0xffffffffu, v, 8);
            if (tx == 0) sred[(nl0 + r) * 16 + l] = v;   // unique writer per slot
        }
    }
    __syncthreads();
    for (int i = tid; i < 512; i += 256) {
        atomicAdd(&sc_out[nb * 512 + i], sred[i]);
    }
}

// ---------------- launcher ----------------
extern "C" void kernel_launch(void* const* d_in, const int* in_sizes, int n_in,
                              void* d_out, int out_size) {
    const float* x     = (const float*)d_in[0];
    const float* A     = (const float*)d_in[1];
    const float* Wx    = (const float*)d_in[2];
    const float* Wh    = (const float*)d_in[3];
    const float* Wattn = (const float*)d_in[4];
    const float* b     = (const float*)d_in[5];
    float* out = (float*)d_out;

    // one-time per-call preprocessing (all graph-capturable kernel launches)
    pack_wh_kernel<<<4096, 256>>>(Wh);
    transposeA_kernel<<<4096, 256>>>(A);
    // Xa = x @ Wx + b  : M=8192, N=4096, K=512
    sgemm_kernel<0><<<dim3(G4 / 64, (NN * TT) / 128), 256>>>(x, Wx, b, NN * TT, G4, DD);
    // P = A2 @ Wattn   : M=1024, N=4096, K=1024 (packed output)
    sgemm_kernel<1><<<dim3(G4 / 64, (NN * 16) / 128), 256>>>(nullptr, Wattn, nullptr,
                                                             NN * 16, G4, HH);
    init_kernel<<<NN, 256>>>(A);

    // sequential recurrence: one fused kernel per timestep
    for (int t = 0; t < TT; t++) {
        step_kernel<<<dim3(64, 2), 256>>>(t, A, out);
    }
}

// round 2
// speedup vs baseline: 2.9699x; 2.9699x over previous
#include <cuda_runtime.h>
#include <math.h>
#include <stdint.h>

// Problem constants
#define NN 64
#define TT 128
#define DD 512
#define HH 1024
#define G4 4096   // 4*H

// ---------------- scratch (device globals; no allocations) ----------------
__device__ float  g_Xa[(NN * TT) * G4];     // 128 MB: x@Wx + b, rows (n*T + t)
__device__ float  g_P[(NN * 16) * G4];      // 16 MB: packed [n][l][c][gate]
__device__ float  g_WhT[HH * G4];           // 16 MB: packed [k][c][gate]
__device__ float  g_A2[(NN * 16) * HH];     // 4 MB:  A2[(n*16+l)][k] = A[n][k][l]
__device__ float2 g_hdup[NN * HH];          // h state, duplicated (h,h) for f32x2
__device__ float  g_cbuf[2][NN * HH];
__device__ float  g_scores[3][NN * 16];     // raw (unscaled) h·Af accumulators

// ---------------- f32x2 / cp.async helpers ----------------
__device__ __forceinline__ unsigned long long fma2(unsigned long long a,
                                                   unsigned long long b,
                                                   unsigned long long c) {
    unsigned long long d;
    asm("fma.rn.f32x2 %0, %1, %2, %3;" : "=l"(d) : "l"(a), "l"(b), "l"(c));
    return d;
}
__device__ __forceinline__ unsigned long long dup2(float v) {
    unsigned long long r;
    asm("mov.b64 %0, {%1, %1};" : "=l"(r) : "f"(v));
    return r;
}
__device__ __forceinline__ unsigned long long pack2(float lo, float hi) {
    unsigned long long r;
    asm("mov.b64 %0, {%1, %2};" : "=l"(r) : "f"(lo), "f"(hi));
    return r;
}
__device__ __forceinline__ float2 unpack2(unsigned long long v) {
    float2 f;
    asm("mov.b64 {%0, %1}, %2;" : "=f"(f.x), "=f"(f.y) : "l"(v));
    return f;
}
__device__ __forceinline__ uint32_t smem_u32(const void* p) {
    return (uint32_t)__cvta_generic_to_shared(p);
}
__device__ __forceinline__ void cp_async16(uint32_t dst, const void* src) {
    asm volatile("cp.async.cg.shared.global [%0], [%1], 16;" :: "r"(dst), "l"(src) : "memory");
}

// ---------------- weight packing ----------------
__global__ void __launch_bounds__(256) pack_wh_kernel(const float* __restrict__ Wh) {
    int idx = blockIdx.x * 256 + threadIdx.x;   // 0 .. 1M-1 over (k, c)
    int k = idx >> 10;
    int c = idx & 1023;
    const float* row = Wh + k * G4;
    float4 v;
    v.x = row[c];
    v.y = row[1024 + c];
    v.z = row[2048 + c];
    v.w = row[3072 + c];
    *(float4*)&g_WhT[idx * 4] = v;
}

// A2[(n*16+l)][k] = A[(n*1024+k)*16 + l]
__global__ void __launch_bounds__(256) transposeA_kernel(const float* __restrict__ A) {
    int idx = blockIdx.x * 256 + threadIdx.x;   // output index, 0 .. 1M-1
    int r = idx >> 10;           // n*16 + l
    int k = idx & 1023;
    int n = r >> 4;
    int l = r & 15;
    g_A2[idx] = A[((n << 10) + k) * 16 + l];
}

// ---------------- generic tiled SGEMM: BM=128, BN=64, BK=16, 256 thr, 8x4 ----
// MODE 0: C = g_Xa, C[row*N+col] = acc + bias[col]
// MODE 1: A = g_A2, C = g_P packed: out[((row*1024)+(col&1023))*4 + (col>>10)]
// Inner product uses packed fma.rn.f32x2: column pairs (n0,n1) and (n2,n3).
template <int MODE>
__global__ void __launch_bounds__(256) sgemm_kernel(const float* __restrict__ Ain,
                                                    const float* __restrict__ B,
                                                    const float* __restrict__ bias,
                                                    int M, int N, int K) {
    __shared__ float As[16][128];
    __shared__ float Bs[16][64];

    const float* Amat = (MODE == 1) ? (const float*)g_A2 : Ain;
    float* C = (MODE == 1) ? (float*)g_P : (float*)g_Xa;

    const int tid = threadIdx.x;
    const int trow = tid >> 4;       // 0..15
    const int tcol = tid & 15;       // 0..15
    const int m0 = blockIdx.y * 128;
    const int n0 = blockIdx.x * 64;

    unsigned long long acc01[8], acc23[8];
#pragma unroll
    for (int i = 0; i < 8; i++) { acc01[i] = 0ULL; acc23[i] = 0ULL; }

    for (int k0 = 0; k0 < K; k0 += 16) {
        // A tile: 128x16 -> transposed As[k][m]
#pragma unroll
        for (int p = 0; p < 2; p++) {
            int i = tid + p * 256;            // 0..511 float4 slots
            int m = i >> 2;
            int kq = (i & 3) * 4;
            float4 v = *(const float4*)&Amat[(long)(m0 + m) * K + k0 + kq];
            As[kq + 0][m] = v.x;
            As[kq + 1][m] = v.y;
            As[kq + 2][m] = v.z;
            As[kq + 3][m] = v.w;
        }
        // B tile: 16x64
        {
            int k = tid >> 4;
            int nq = (tid & 15) * 4;
            *(float4*)&Bs[k][nq] = *(const float4*)&B[(long)(k0 + k) * N + n0 + nq];
        }
        __syncthreads();

#pragma unroll
        for (int kk = 0; kk < 16; kk++) {
            float a0[8];
            float4 av0 = *(float4*)&As[kk][trow * 8];
            float4 av1 = *(float4*)&As[kk][trow * 8 + 4];
            a0[0] = av0.x; a0[1] = av0.y; a0[2] = av0.z; a0[3] = av0.w;
            a0[4] = av1.x; a0[5] = av1.y; a0[6] = av1.z; a0[7] = av1.w;
            ulonglong2 bv = *(ulonglong2*)&Bs[kk][tcol * 4];
#pragma unroll
            for (int i = 0; i < 8; i++) {
                unsigned long long ad = dup2(a0[i]);
                acc01[i] = fma2(ad, bv.x, acc01[i]);
                acc23[i] = fma2(ad, bv.y, acc23[i]);
            }
        }
        __syncthreads();
    }

#pragma unroll
    for (int i = 0; i < 8; i++) {
        int row = m0 + trow * 8 + i;
        int colb = n0 + tcol * 4;
        float2 a01 = unpack2(acc01[i]);
        float2 a23 = unpack2(acc23[i]);
        if (MODE == 0) {
            float4 bv = *(const float4*)&bias[colb];
            float4 o;
            o.x = a01.x + bv.x;
            o.y = a01.y + bv.y;
            o.z = a23.x + bv.z;
            o.w = a23.y + bv.w;
            *(float4*)&C[(long)row * N + colb] = o;
        } else {
            float av[4] = {a01.x, a01.y, a23.x, a23.y};
#pragma unroll
            for (int j = 0; j < 4; j++) {
                int col = colb + j;
                int g = col >> 10;
                int cl = col & 1023;
                C[((long)row * 1024 + cl) * 4 + g] = av[j];
            }
        }
    }
}

// ---------------- init: h0 = c0 = mean(Af), scores0 = h0·Af ----------------
__global__ void __launch_bounds__(256) init_kernel(const float* __restrict__ A) {
    const int n = blockIdx.x;
    const int tid = threadIdx.x;
    __shared__ float sc[256][16];

    float accl[16];
#pragma unroll
    for (int l = 0; l < 16; l++) accl[l] = 0.0f;

    for (int h = tid; h < HH; h += 256) {
        const float* ar = A + ((n << 10) + h) * 16;
        float a[16];
        float4 v0 = *(const float4*)&ar[0];
        float4 v1 = *(const float4*)&ar[4];
        float4 v2 = *(const float4*)&ar[8];
        float4 v3 = *(const float4*)&ar[12];
        a[0]=v0.x; a[1]=v0.y; a[2]=v0.z; a[3]=v0.w;
        a[4]=v1.x; a[5]=v1.y; a[6]=v1.z; a[7]=v1.w;
        a[8]=v2.x; a[9]=v2.y; a[10]=v2.z; a[11]=v2.w;
        a[12]=v3.x; a[13]=v3.y; a[14]=v3.z; a[15]=v3.w;
        float s = 0.0f;
#pragma unroll
        for (int l = 0; l < 16; l++) s += a[l];
        s *= (1.0f / 16.0f);
        g_hdup[(n << 10) + h] = make_float2(s, s);
        g_cbuf[0][(n << 10) + h] = s;
#pragma unroll
        for (int l = 0; l < 16; l++) accl[l] += s * a[l];
    }
#pragma unroll
    for (int l = 0; l < 16; l++) sc[tid][l] = accl[l];
    __syncthreads();
    if (tid < 16) {
        float s = 0.0f;
        for (int j = 0; j < 256; j++) s += sc[j][tid];
        g_scores[0][n * 16 + tid] = s;
        g_scores[1][n * 16 + tid] = 0.0f;
        g_scores[2][n * 16 + tid] = 0.0f;
    }
}

// ---------------- fused step: softmax + (h@Wh + w@P + Xa) + LSTM + next scores
// cp.async double-buffered staging of Wh tile + duplicated-h tile, 32-k blocks.
__global__ void __launch_bounds__(256) step_kernel(int t, const float* __restrict__ A,
                                                   float* __restrict__ out) {
    const int tid = threadIdx.x;
    const int tx = tid & 15;         // c within block
    const int ty = tid >> 4;         // n-pair index
    const int cb = blockIdx.x;       // 0..63
    const int nb = blockIdx.y;       // 0..1
    const int c = cb * 16 + tx;
    const int cb16 = cb * 16;
    const int nb32 = nb * 32;
    const int nl0 = ty * 2;
    const int nl1 = nl0 + 1;
    const int n0 = nb32 + nl0;
    const int n1 = n0 + 1;

    const int prev = t & 1;
    const int cur = prev ^ 1;
    const float* c_prev = g_cbuf[prev];
    const float* sc_in = g_scores[t % 3];
    float* sc_out = g_scores[(t + 1) % 3];
    float* sc_zero = g_scores[(t + 2) % 3];

    __shared__ float4 sW[2][32][16];   // [buf][k_local][tx] : 4 gate weights
    __shared__ float2 sH[2][32][32];   // [buf][n_local][k_local] : (h,h)
    __shared__ float ws[32][16];
    __shared__ float sred[512];

#define STAGE(kb, b) do {                                                          \
        int k0_ = (kb) << 5;                                                       \
        _Pragma("unroll")                                                          \
        for (int i_ = 0; i_ < 2; i_++) {                                           \
            int s_ = tid + i_ * 256;                                               \
            int kl_ = s_ >> 4, txi_ = s_ & 15;                                     \
            cp_async16(smem_u32(&sW[b][kl_][txi_]),                                \
                       &g_WhT[(((k0_ + kl_) << 10) + cb16 + txi_) << 2]);          \
        }                                                                          \
        _Pragma("unroll")                                                          \
        for (int i_ = 0; i_ < 2; i_++) {                                           \
            int s_ = tid + i_ * 256;                                               \
            int nl_ = s_ >> 4, kq_ = (s_ & 15) << 1;                               \
            cp_async16(smem_u32(&sH[b][nl_][kq_]),                                 \
                       &g_hdup[((nb32 + nl_) << 10) + k0_ + kq_]);                 \
        }                                                                          \
        asm volatile("cp.async.commit_group;" ::: "memory");                       \
    } while (0)

    // prefetch block 0
    STAGE(0, 0);

    // per-CTA redundant softmax over the 32 rows it owns (overlaps the prefetch)
    if (tid < 32) {
        float s[16];
        float m = -1e30f;
#pragma unroll
        for (int l = 0; l < 16; l++) {
            s[l] = sc_in[(nb32 + tid) * 16 + l] * 0.03125f;  // 1/sqrt(1024)
            m = fmaxf(m, s[l]);
        }
        float sum = 0.0f;
#pragma unroll
        for (int l = 0; l < 16; l++) { s[l] = expf(s[l] - m); sum += s[l]; }
        float inv = 1.0f / sum;
#pragma unroll
        for (int l = 0; l < 16; l++) ws[tid][l] = s[l] * inv;
    }
    // zero the buffer that step t+1 will accumulate into
    if (cb == 0) {
        sc_zero[nb * 512 + tid] = 0.0f;
        sc_zero[nb * 512 + tid + 256] = 0.0f;
    }

    // init accumulators from precomputed Xa (bias already folded in)
    unsigned long long acc01_0, acc23_0, acc01_1, acc23_1;
    {
        const float* xa0 = g_Xa + ((long)(n0 * TT + t)) * G4 + c;
        const float* xa1 = g_Xa + ((long)(n1 * TT + t)) * G4 + c;
        acc01_0 = pack2(xa0[0], xa0[1 << 10]);
        acc23_0 = pack2(xa0[2 << 10], xa0[3 << 10]);
        acc01_1 = pack2(xa1[0], xa1[1 << 10]);
        acc23_1 = pack2(xa1[2 << 10], xa1[3 << 10]);
    }

    // main recurrent GEMM: a += h_prev @ Wh, 32 k-blocks of 32, double-buffered
    int buf = 0;
    for (int kb = 0; kb < 32; kb++) {
        if (kb < 31) {
            STAGE(kb + 1, buf ^ 1);
            asm volatile("cp.async.wait_group 1;" ::: "memory");
        } else {
            asm volatile("cp.async.wait_group 0;" ::: "memory");
        }
        __syncthreads();

#pragma unroll 8
        for (int k = 0; k < 32; k++) {
            ulonglong2 w = *(const ulonglong2*)&sW[buf][k][tx];
            unsigned long long h0 = *(const unsigned long long*)&sH[buf][nl0][k];
            unsigned long long h1 = *(const unsigned long long*)&sH[buf][nl1][k];
            acc01_0 = fma2(h0, w.x, acc01_0);
            acc23_0 = fma2(h0, w.y, acc23_0);
            acc01_1 = fma2(h1, w.x, acc01_1);
            acc23_1 = fma2(h1, w.y, acc23_1);
        }
        buf ^= 1;
        __syncthreads();
    }
#undef STAGE

    // attention contribution: a += w @ P  (P packed [n][l][c][gate])
    const ulonglong2* P2 = (const ulonglong2*)g_P;
#pragma unroll
    for (int l = 0; l < 16; l++) {
        unsigned long long w0 = dup2(ws[nl0][l]);
        unsigned long long w1 = dup2(ws[nl1][l]);
        ulonglong2 p0 = P2[((n0 * 16 + l) << 10) + c];
        ulonglong2 p1 = P2[((n1 * 16 + l) << 10) + c];
        acc01_0 = fma2(w0, p0.x, acc01_0);
        acc23_0 = fma2(w0, p0.y, acc23_0);
        acc01_1 = fma2(w1, p1.x, acc01_1);
        acc23_1 = fma2(w1, p1.y, acc23_1);
    }

    // LSTM cell update + output write
    float hn[2];
#pragma unroll
    for (int r = 0; r < 2; r++) {
        int n = n0 + r;
        float2 a01 = unpack2(r == 0 ? acc01_0 : acc01_1);
        float2 a23 = unpack2(r == 0 ? acc23_0 : acc23_1);
        float ig = 1.0f / (1.0f + expf(-a01.x));
        float fg = 1.0f / (1.0f + expf(-a01.y));
        float og = 1.0f / (1.0f + expf(-a23.x));
        float gg = tanhf(a23.y);
        float cp = c_prev[(n << 10) + c];
        float cn = fg * cp + ig * gg;
        float h = og * tanhf(cn);
        g_cbuf[cur][(n << 10) + c] = cn;
        g_hdup[(n << 10) + c] = make_float2(h, h);
        out[((long)(n * TT + t)) * HH + c] = h;
        hn[r] = h;
    }

    // next-step score partials: scores[n][l] += sum_c h_new[n][c] * A[n][c][l]
#pragma unroll
    for (int r = 0; r < 2; r++) {
        int n = n0 + r;
        const float* ar = A + (((long)(n << 10) + c)) * 16;
        float a[16];
        float4 v0 = *(const float4*)&ar[0];
        float4 v1 = *(const float4*)&ar[4];
        float4 v2 = *(const float4*)&ar[8];
        float4 v3 = *(const float4*)&ar[12];
        a[0]=v0.x; a[1]=v0.y; a[2]=v0.z; a[3]=v0.w;
        a[4]=v1.x; a[5]=v1.y; a[6]=v1.z; a[7]=v1.w;
        a[8]=v2.x; a[9]=v2.y; a[10]=v2.z; a[11]=v2.w;
        a[12]=v3.x; a[13]=v3.y; a[14]=v3.z; a[15]=v3.w;
#pragma unroll
        for (int l = 0; l < 16; l++) {
            float v = hn[r] * a[l];
            // reduce over the 16 tx lanes (halves of the warp stay separate)
            v += __shfl_xor_sync(0xffffffffu, v, 1);
            v += __shfl_xor_sync(0xffffffffu, v, 2);
            v += __shfl_xor_sync(0xffffffffu, v, 4);
            v += __shfl_xor_sync(0xffffffffu, v, 8);
            if (tx == 0) sred[(nl0 + r) * 16 + l] = v;   // unique writer per slot
        }
    }
    __syncthreads();
    for (int i = tid; i < 512; i += 256) {
        atomicAdd(&sc_out[nb * 512 + i], sred[i]);
    }
}

// ---------------- launcher ----------------
extern "C" void kernel_launch(void* const* d_in, const int* in_sizes, int n_in,
                              void* d_out, int out_size) {
    const float* x     = (const float*)d_in[0];
    const float* A     = (const float*)d_in[1];
    const float* Wx    = (const float*)d_in[2];
    const float* Wh    = (const float*)d_in[3];
    const float* Wattn = (const float*)d_in[4];
    const float* b     = (const float*)d_in[5];
    float* out = (float*)d_out;

    // one-time per-call preprocessing (all graph-capturable kernel launches)
    pack_wh_kernel<<<4096, 256>>>(Wh);
    transposeA_kernel<<<4096, 256>>>(A);
    // Xa = x @ Wx + b  : M=8192, N=4096, K=512
    sgemm_kernel<0><<<dim3(G4 / 64, (NN * TT) / 128), 256>>>(x, Wx, b, NN * TT, G4, DD);
    // P = A2 @ Wattn   : M=1024, N=4096, K=1024 (packed output)
    sgemm_kernel<1><<<dim3(G4 / 64, (NN * 16) / 128), 256>>>(nullptr, Wattn, nullptr,
                                                             NN * 16, G4, HH);
    init_kernel<<<NN, 256>>>(A);

    // sequential recurrence: one fused kernel per timestep
    for (int t = 0; t < TT; t++) {
        step_kernel<<<dim3(64, 2), 256>>>(t, A, out);
    }
}